// round 8
// baseline (speedup 1.0000x reference)
#include <cuda_runtime.h>

// Problem shapes (fixed by the dataset problem)
#define BB 8
#define CC 64
#define HH 256
#define WW 256
#define HW (HH*WW)       // 65536

// Tile geometry: 32 wide x 16 tall, 512 threads.
#define TTX 32
#define TTY 16
#define NT  512
#define GXX (TTX+6)      // 38: gray region width  (halo 3)
#define GYY (TTY+6)      // 22: gray region height
#define DXX (TTX+2)      // 34: DoG region width   (halo 1)
#define DYY (TTY+2)      // 18: DoG region height
#define DN  (DXX*DYY)    // 612

// Gray phase float4 layout: span x0-4 .. x0+35 = 10 float4 per row, 22 rows.
#define NJ  10
#define NP  (GYY*NJ)     // 220 float4 positions
#define NTASK (NP*2)     // 440 = 2-way channel split

// ---------------------------------------------------------------------------
// Fully fused:
//   gray = mean_c(x) over tile+halo(3)   [x read #1: float4, DRAM first-touch]
//   -> DoG(5x5, zero-pad) -> Sobel(3x3, zero-pad on DoG) -> att in smem
//   -> out = x * (1 + att)               [x read #2: float4, L1/L2 hit]
// Gray phase is float4-vectorized (the 38-wide region lives inside a
// 4-aligned 40-wide span; W=256 and 32-aligned tiles mean every float4 is
// fully in-image or fully in the zero-pad) and 2-way channel-split so 440 of
// 512 threads are active with only 32 loads each.
// ---------------------------------------------------------------------------
__global__ void __launch_bounds__(NT, 3)
fused_kernel(const float* __restrict__ x,
             const float* __restrict__ gw,
             const float* __restrict__ gbv,
             float* __restrict__ out) {
    __shared__ float  sg[GYY][GXX + 2];  // gray region (padded cols)
    __shared__ float4 spart[NP];         // channel-half partial sums
    __shared__ float  sd[DYY][DXX + 2];  // dog region
    __shared__ float  sa[TTY][TTX];      // att (1 + sigmoid)
    __shared__ float  kd[25];            // DoG weights (gk1 - gk2)

    const int tid = threadIdx.x;

    if (tid == 0) {
        // Normalized gaussian kernels exactly like the reference (fp32).
        float w1[25], w2[25];
        float s1 = 0.f, s2 = 0.f;
        #pragma unroll
        for (int i = 0; i < 25; ++i) {
            float dx = (float)(i / 5) - 2.0f;
            float dy = (float)(i % 5) - 2.0f;
            float r2 = dx * dx + dy * dy;
            float a = expf(-r2 * 0.5f);     // sigma = 1
            float b = expf(-r2 * 0.125f);   // sigma = 2
            w1[i] = a; w2[i] = b;
            s1 += a;  s2 += b;
        }
        float i1 = 1.0f / s1, i2 = 1.0f / s2;
        #pragma unroll
        for (int i = 0; i < 25; ++i) kd[i] = w1[i] * i1 - w2[i] * i2;
    }

    const int b  = blockIdx.z;
    const int x0 = blockIdx.x * TTX;
    const int y0 = blockIdx.y * TTY;
    const float* xb = x + (size_t)b * CC * HW;

    // ---- Phase 1a: float4 gray partial sums (2-way channel split) ----
    float4 acc = make_float4(0.f, 0.f, 0.f, 0.f);
    int pos = -1, half = 0;
    if (tid < NTASK) {
        half = (tid >= NP);
        pos  = tid - (half ? NP : 0);
        int r  = pos / NJ;
        int j  = pos - r * NJ;
        int gy = y0 - 3 + r;
        int gx4 = x0 - 4 + 4 * j;
        if ((unsigned)gy < HH && gx4 >= 0 && gx4 + 3 < WW) {
            const float4* p = (const float4*)(xb + (size_t)gy * WW + gx4)
                            + (size_t)half * 32 * (HW / 4);
            float4 a0 = make_float4(0.f,0.f,0.f,0.f);
            float4 a1 = make_float4(0.f,0.f,0.f,0.f);
            float4 a2 = make_float4(0.f,0.f,0.f,0.f);
            float4 a3 = make_float4(0.f,0.f,0.f,0.f);
            #pragma unroll
            for (int cc = 0; cc < 32; cc += 4) {
                float4 v0 = __ldg(p + (size_t)(cc + 0) * (HW / 4));
                float4 v1 = __ldg(p + (size_t)(cc + 1) * (HW / 4));
                float4 v2 = __ldg(p + (size_t)(cc + 2) * (HW / 4));
                float4 v3 = __ldg(p + (size_t)(cc + 3) * (HW / 4));
                a0.x += v0.x; a0.y += v0.y; a0.z += v0.z; a0.w += v0.w;
                a1.x += v1.x; a1.y += v1.y; a1.z += v1.z; a1.w += v1.w;
                a2.x += v2.x; a2.y += v2.y; a2.z += v2.z; a2.w += v2.w;
                a3.x += v3.x; a3.y += v3.y; a3.z += v3.z; a3.w += v3.w;
            }
            acc.x = (a0.x + a1.x) + (a2.x + a3.x);
            acc.y = (a0.y + a1.y) + (a2.y + a3.y);
            acc.z = (a0.z + a1.z) + (a2.z + a3.z);
            acc.w = (a0.w + a1.w) + (a2.w + a3.w);
        }
        if (half) spart[pos] = acc;
    }
    __syncthreads();

    // ---- Phase 1b: combine halves, scatter into sg (drop c=-1 and c=38) ----
    if (tid < NP && !half) {
        float4 o = spart[pos];
        const float sc = 1.0f / (float)CC;
        float g0 = (o.x + acc.x) * sc;
        float g1 = (o.y + acc.y) * sc;
        float g2 = (o.z + acc.z) * sc;
        float g3 = (o.w + acc.w) * sc;
        int r = pos / NJ;
        int j = pos - r * NJ;
        int c0 = 4 * j - 1;                 // sg columns c0..c0+3
        if (c0 >= 0)        sg[r][c0    ] = g0;
                            sg[r][c0 + 1] = g1;
                            sg[r][c0 + 2] = g2;
        if (c0 + 3 < GXX)   sg[r][c0 + 3] = g3;
    }
    __syncthreads();

    // ---- Phase 2: DoG on tile + halo(1); out-of-image DoG forced to 0 ----
    for (int i = tid; i < DN; i += NT) {
        int r = i / DXX, c = i - r * DXX;
        int gy = y0 - 1 + r, gx = x0 - 1 + c;
        float vv = 0.f;
        if ((unsigned)gy < HH && (unsigned)gx < WW) {
            float a2 = 0.f;
            #pragma unroll
            for (int ki = 0; ki < 5; ++ki)
                #pragma unroll
                for (int kj = 0; kj < 5; ++kj)
                    a2 += kd[ki * 5 + kj] * sg[r + ki][c + kj];
            vv = a2;
        }
        sd[r][c] = vv;
    }
    __syncthreads();

    // ---- Phase 3: Sobel -> magnitude -> sigmoid gate (one pixel/thread) ----
    {
        const int py = tid >> 5;       // 0..15
        const int px = tid & 31;       // 0..31
        float d00 = sd[py    ][px    ], d01 = sd[py    ][px + 1], d02 = sd[py    ][px + 2];
        float d10 = sd[py + 1][px    ],                            d12 = sd[py + 1][px + 2];
        float d20 = sd[py + 2][px    ], d21 = sd[py + 2][px + 1], d22 = sd[py + 2][px + 2];
        float gxv = (d02 - d00) + 2.0f * (d12 - d10) + (d22 - d20);
        float gyv = (d20 - d00) + 2.0f * (d21 - d01) + (d22 - d02);
        float mag = sqrtf(gxv * gxv + gyv * gyv + 1e-6f);
        float tv  = mag * gw[0] + gbv[0];
        sa[py][px] = 1.0f + 1.0f / (1.0f + expf(-tv));
    }
    __syncthreads();

    // ---- Phase 4: out = x * att, float4, re-read of x hits L1/L2 ----
    // Tile per channel = 16 rows x 8 float4; 8192 float4 total, 16 per thread.
    #pragma unroll 4
    for (int f = tid; f < (TTY * TTX / 4) * CC; f += NT) {
        int c  = f >> 7;               // channel
        int q  = f & 127;              // float4 slot within tile
        int r  = q >> 3;               // row 0..15
        int c4 = (q & 7) << 2;         // col 0,4,...,28
        size_t off = (size_t)c * HW + (size_t)(y0 + r) * WW + (x0 + c4);
        float4 v = __ldg((const float4*)(xb + off));
        float4 a = *(const float4*)&sa[r][c4];
        v.x *= a.x; v.y *= a.y; v.z *= a.z; v.w *= a.w;
        *(float4*)(out + (size_t)b * CC * HW + off) = v;
    }
}

// ---------------------------------------------------------------------------
extern "C" void kernel_launch(void* const* d_in, const int* in_sizes, int n_in,
                              void* d_out, int out_size) {
    const float* x  = (const float*)d_in[0];
    const float* gw = (const float*)d_in[1];
    const float* gb = (const float*)d_in[2];
    float* out = (float*)d_out;

    dim3 grid(WW / TTX, HH / TTY, BB);   // 8 x 16 x 8 = 1024 blocks
    fused_kernel<<<grid, NT>>>(x, gw, gb, out);
}

// round 10
// speedup vs baseline: 1.0320x; 1.0320x over previous
#include <cuda_runtime.h>

// Problem shapes (fixed by the dataset problem)
#define BB 8
#define CC 64
#define HH 256
#define WW 256
#define HW (HH*WW)       // 65536

// Tile geometry: 32 wide x 16 tall, 512 threads.
#define TTX 32
#define TTY 16
#define NT  512
#define GXX (TTX+6)      // 38: gray region width  (halo 3)
#define GYY (TTY+6)      // 22: gray region height
#define DXX (TTX+2)      // 34: DoG region width   (halo 1)
#define DYY (TTY+2)      // 18: DoG region height
#define DN  (DXX*DYY)    // 612

// Gray phase float4 layout: span x0-4 .. x0+35 = 10 float4 per row, 22 rows.
#define NJ  10
#define NP  (GYY*NJ)     // 220 float4 positions
#define NTASK (NP*2)     // 440 = 2-way channel split

// ---------------------------------------------------------------------------
// Fully fused:
//   gray = mean_c(x) over tile+halo(3)   [x read #1: float4, DRAM first-touch]
//   -> DoG(5x5, zero-pad) -> Sobel(3x3, zero-pad on DoG) -> att in smem
//   -> out = x * (1 + att)               [x read #2: float4, L2 hit;
//                                         out stored with __stcs so the
//                                         write stream does not evict x
//                                         from L2 (x ~= L2 capacity)]
// ---------------------------------------------------------------------------
__global__ void __launch_bounds__(NT, 3)
fused_kernel(const float* __restrict__ x,
             const float* __restrict__ gw,
             const float* __restrict__ gbv,
             float* __restrict__ out) {
    __shared__ float  sg[GYY][GXX + 2];  // gray region (padded cols)
    __shared__ float4 spart[NP];         // channel-half partial sums
    __shared__ float  sd[DYY][DXX + 2];  // dog region
    __shared__ float  sa[TTY][TTX];      // att (1 + sigmoid)
    __shared__ float  kd[25];            // DoG weights (gk1 - gk2)

    const int tid = threadIdx.x;

    if (tid == 0) {
        // Normalized gaussian kernels exactly like the reference (fp32).
        float w1[25], w2[25];
        float s1 = 0.f, s2 = 0.f;
        #pragma unroll
        for (int i = 0; i < 25; ++i) {
            float dx = (float)(i / 5) - 2.0f;
            float dy = (float)(i % 5) - 2.0f;
            float r2 = dx * dx + dy * dy;
            float a = expf(-r2 * 0.5f);     // sigma = 1
            float b = expf(-r2 * 0.125f);   // sigma = 2
            w1[i] = a; w2[i] = b;
            s1 += a;  s2 += b;
        }
        float i1 = 1.0f / s1, i2 = 1.0f / s2;
        #pragma unroll
        for (int i = 0; i < 25; ++i) kd[i] = w1[i] * i1 - w2[i] * i2;
    }

    const int b  = blockIdx.z;
    const int x0 = blockIdx.x * TTX;
    const int y0 = blockIdx.y * TTY;
    const float* xb = x + (size_t)b * CC * HW;

    // ---- Phase 1a: float4 gray partial sums (2-way channel split) ----
    float4 acc = make_float4(0.f, 0.f, 0.f, 0.f);
    int pos = -1, half = 0;
    if (tid < NTASK) {
        half = (tid >= NP);
        pos  = tid - (half ? NP : 0);
        int r  = pos / NJ;
        int j  = pos - r * NJ;
        int gy = y0 - 3 + r;
        int gx4 = x0 - 4 + 4 * j;
        if ((unsigned)gy < HH && gx4 >= 0 && gx4 + 3 < WW) {
            const float4* p = (const float4*)(xb + (size_t)gy * WW + gx4)
                            + (size_t)half * 32 * (HW / 4);
            float4 a0 = make_float4(0.f,0.f,0.f,0.f);
            float4 a1 = make_float4(0.f,0.f,0.f,0.f);
            float4 a2 = make_float4(0.f,0.f,0.f,0.f);
            float4 a3 = make_float4(0.f,0.f,0.f,0.f);
            #pragma unroll
            for (int cc = 0; cc < 32; cc += 4) {
                float4 v0 = __ldg(p + (size_t)(cc + 0) * (HW / 4));
                float4 v1 = __ldg(p + (size_t)(cc + 1) * (HW / 4));
                float4 v2 = __ldg(p + (size_t)(cc + 2) * (HW / 4));
                float4 v3 = __ldg(p + (size_t)(cc + 3) * (HW / 4));
                a0.x += v0.x; a0.y += v0.y; a0.z += v0.z; a0.w += v0.w;
                a1.x += v1.x; a1.y += v1.y; a1.z += v1.z; a1.w += v1.w;
                a2.x += v2.x; a2.y += v2.y; a2.z += v2.z; a2.w += v2.w;
                a3.x += v3.x; a3.y += v3.y; a3.z += v3.z; a3.w += v3.w;
            }
            acc.x = (a0.x + a1.x) + (a2.x + a3.x);
            acc.y = (a0.y + a1.y) + (a2.y + a3.y);
            acc.z = (a0.z + a1.z) + (a2.z + a3.z);
            acc.w = (a0.w + a1.w) + (a2.w + a3.w);
        }
        if (half) spart[pos] = acc;
    }
    __syncthreads();

    // ---- Phase 1b: combine halves, scatter into sg (drop c=-1 and c=38) ----
    if (tid < NP && !half) {
        float4 o = spart[pos];
        const float sc = 1.0f / (float)CC;
        float g0 = (o.x + acc.x) * sc;
        float g1 = (o.y + acc.y) * sc;
        float g2 = (o.z + acc.z) * sc;
        float g3 = (o.w + acc.w) * sc;
        int r = pos / NJ;
        int j = pos - r * NJ;
        int c0 = 4 * j - 1;                 // sg columns c0..c0+3
        if (c0 >= 0)        sg[r][c0    ] = g0;
                            sg[r][c0 + 1] = g1;
                            sg[r][c0 + 2] = g2;
        if (c0 + 3 < GXX)   sg[r][c0 + 3] = g3;
    }
    __syncthreads();

    // ---- Phase 2: DoG on tile + halo(1); out-of-image DoG forced to 0 ----
    for (int i = tid; i < DN; i += NT) {
        int r = i / DXX, c = i - r * DXX;
        int gy = y0 - 1 + r, gx = x0 - 1 + c;
        float vv = 0.f;
        if ((unsigned)gy < HH && (unsigned)gx < WW) {
            float a2 = 0.f;
            #pragma unroll
            for (int ki = 0; ki < 5; ++ki)
                #pragma unroll
                for (int kj = 0; kj < 5; ++kj)
                    a2 += kd[ki * 5 + kj] * sg[r + ki][c + kj];
            vv = a2;
        }
        sd[r][c] = vv;
    }
    __syncthreads();

    // ---- Phase 3: Sobel -> magnitude -> sigmoid gate (one pixel/thread) ----
    {
        const int py = tid >> 5;       // 0..15
        const int px = tid & 31;       // 0..31
        float d00 = sd[py    ][px    ], d01 = sd[py    ][px + 1], d02 = sd[py    ][px + 2];
        float d10 = sd[py + 1][px    ],                            d12 = sd[py + 1][px + 2];
        float d20 = sd[py + 2][px    ], d21 = sd[py + 2][px + 1], d22 = sd[py + 2][px + 2];
        float gxv = (d02 - d00) + 2.0f * (d12 - d10) + (d22 - d20);
        float gyv = (d20 - d00) + 2.0f * (d21 - d01) + (d22 - d02);
        float mag = sqrtf(gxv * gxv + gyv * gyv + 1e-6f);
        float tv  = mag * gw[0] + gbv[0];
        sa[py][px] = 1.0f + 1.0f / (1.0f + expf(-tv));
    }
    __syncthreads();

    // ---- Phase 4: out = x * att; x re-read hits L2, out stored streaming ----
    // Tile per channel = 16 rows x 8 float4; 8192 float4 total, 16 per thread.
    #pragma unroll 4
    for (int f = tid; f < (TTY * TTX / 4) * CC; f += NT) {
        int c  = f >> 7;               // channel
        int q  = f & 127;              // float4 slot within tile
        int r  = q >> 3;               // row 0..15
        int c4 = (q & 7) << 2;         // col 0,4,...,28
        size_t off = (size_t)c * HW + (size_t)(y0 + r) * WW + (x0 + c4);
        float4 v = __ldg((const float4*)(xb + off));
        float4 a = *(const float4*)&sa[r][c4];
        v.x *= a.x; v.y *= a.y; v.z *= a.z; v.w *= a.w;
        __stcs((float4*)(out + (size_t)b * CC * HW + off), v);
    }
}

// ---------------------------------------------------------------------------
extern "C" void kernel_launch(void* const* d_in, const int* in_sizes, int n_in,
                              void* d_out, int out_size) {
    const float* x  = (const float*)d_in[0];
    const float* gw = (const float*)d_in[1];
    const float* gb = (const float*)d_in[2];
    float* out = (float*)d_out;

    dim3 grid(WW / TTX, HH / TTY, BB);   // 8 x 16 x 8 = 1024 blocks
    fused_kernel<<<grid, NT>>>(x, gw, gb, out);
}